// round 13
// baseline (speedup 1.0000x reference)
#include <cuda_runtime.h>
#include <cstddef>

#define NA 192
#define TT 80
#define NC 5
#define TILE 32
#define HTILE 16
#define NTHREADS 256
#define NPAIRS 21
#define NUNITS (TT * NPAIRS * 2)   // 3360 half-tile units
#define NBLOCKS 1120               // one full wave (148 SM x 8 blocks = 1184 slots)
#define UPB (NUNITS / NBLOCKS)     // 3 units per block
#define MAGIC 12582912.0f          // 1.5 * 2^23: add/sub rounds to nearest int

__constant__ unsigned char cIT[NPAIRS] = {0,0,0,0,0,0,1,1,1,1,1,2,2,2,2,3,3,3,4,4,5};
__constant__ unsigned char cJT[NPAIRS] = {0,1,2,3,4,5,1,2,3,4,5,2,3,4,5,3,4,5,4,5,5};

__global__ __launch_bounds__(NTHREADS) void veh_coll_kernel(
    const float* __restrict__ traj,        // (NA, T, 4)
    const float* __restrict__ centroids,   // (NA, NC, 4)
    const float* __restrict__ pen,         // (NA, NA)
    float* __restrict__ out,               // [pen (T,NA,NA)][mask (T,NA,NA)]
    int write_mask)
{
    __shared__ float4 sPose[2 * TILE];         // [0,32) = I tile, [32,64) = J tile
    __shared__ float  sG0[2 * TILE];           // s_0
    __shared__ float  sGd[2 * TILE];           // delta
    __shared__ float  sGi[2 * TILE];           // 1/delta
    __shared__ float  sTile[HTILE][TILE + 2];  // pv staged for transpose (stride 34)

    const int tid = threadIdx.x;
    const unsigned P = (unsigned)TT * NA * NA;

    #pragma unroll 1
    for (int k = 0; k < UPB; ++k) {
        if (k > 0) __syncthreads();            // protect smem from previous unit

        const int u   = blockIdx.x + k * NBLOCKS;
        const int t   = u % TT;
        const int pr2 = u / TT;
        const int pr  = pr2 >> 1;
        const int ih  = (pr2 & 1) * HTILE;     // i half-offset within tile
        const int it  = cIT[pr];
        const int jt  = cJT[pr];

        // ---- Stage per-agent pose + uniform circle-grid parameters ----
        if (tid < 2 * TILE) {
            int side = tid >> 5, loc = tid & 31;
            int a = (side ? jt : it) * TILE + loc;
            float4 tr = *reinterpret_cast<const float4*>(traj + (a * TT + t) * 4);
            float inv = rsqrtf(tr.z * tr.z + tr.w * tr.w);
            sPose[tid] = make_float4(tr.x, tr.y, tr.z * inv, tr.w * inv);
            float s0 = centroids[(a * NC + 0) * 4];
            float s4 = centroids[(a * NC + 4) * 4];
            float dd = (s4 - s0) * 0.25f;      // uniform spacing (linspace frac)
            sG0[tid] = s0;
            sGd[tid] = dd;
            sGi[tid] = __frcp_rn(dd);
        }
        __syncthreads();

        // ---- lane = j local; each warp walks 2 i's of this half-tile ----
        const int jl   = tid & 31;
        const int warp = tid >> 5;
        const int jg   = jt * TILE + jl;

        const float4 pj   = sPose[TILE + jl];
        const float  sj0  = sG0[TILE + jl];
        const float  dj   = sGd[TILE + jl];
        const float  idj  = sGi[TILE + jl];
        const float  offj = -sj0 * idj;

        #pragma unroll
        for (int w = 0; w < HTILE / (NTHREADS / 32); ++w) {
            const int il = ih + warp + w * (NTHREADS / 32);
            const int ig = it * TILE + il;

            const float4 pi = sPose[il];       // broadcast
            const float si0 = sG0[il];
            const float di  = sGd[il];

            float dx = pi.x - pj.x;
            float dy = pi.y - pj.y;
            float a  = fmaf(dy, pi.w, dx * pi.z);     // base . h_i
            float b  = fmaf(dy, pj.w, dx * pj.z);     // base . h_j
            float g  = fmaf(pi.w, pj.w, pi.z * pj.z); // h_i . h_j
            float B  = fmaf(dy, dy, dx * dx);
            float a2  = a + a;
            float nb2 = -(b + b);
            float ng2 = -(g + g);
            float gi  = g * idj;                      // yn = x*gi + byn
            float byn = fmaf(b, idj, offj);

            float d2c[NC];
            #pragma unroll
            for (int c = 0; c < NC; c++) {
                float x  = fmaf((float)c, di, si0);   // i circle offset
                float yn = fmaf(x, gi, byn);          // grid coord of w* = b + g x
                float r  = fminf(fmaxf(yn, 0.0f), 4.0f);
                r        = __fadd_rn(r, MAGIC);       // round-to-nearest-int
                r        = __fadd_rn(r, -MAGIC);
                float wv = fmaf(r, dj, sj0);          // nearest j circle offset
                float uu = fmaf(x, x + a2, B);        // B + x^2 + 2ax
                float tm = fmaf(ng2, x, nb2);         // -2b - 2gx
                d2c[c]   = fmaf(wv, wv + tm, uu);     // exact min over d for this c
            }
            float m = fminf(fminf(fminf(d2c[0], d2c[1]), fminf(d2c[2], d2c[3])), d2c[4]);

            m = fmaxf(m, 1e-30f);
            float md = m * rsqrtf(m);                 // sqrt(m) via 1 MUFU + 1 mul
            float pd = pen[ig * NA + jg];
            float pv = 1.0f - __fdividef(md, pd);
            const unsigned idx = ((unsigned)t * NA + ig) * NA + jg;
            out[idx] = pv;
            if (write_mask)
                out[P + idx] = (pv >= 0.0f && ig != jg) ? 1.0f : 0.0f;
            sTile[il - ih][jl] = pv;
        }

        // ---- Transposed write for off-diagonal tile pairs ----
        if (it != jt) {
            __syncthreads();
            #pragma unroll
            for (int q = 0; q < (HTILE * TILE) / NTHREADS; ++q) {
                int e  = tid + q * NTHREADS;
                int jj = e >> 4;                      // 0..31 (j index)
                int ii = e & 15;                      // 0..15 (i within half)
                float pv = sTile[ii][jj];             // stride 34: conflict-free
                const unsigned idxT =
                    ((unsigned)t * NA + jt * TILE + jj) * NA + it * TILE + ih + ii;
                out[idxT] = pv;
                if (write_mask)
                    out[P + idxT] = (pv >= 0.0f) ? 1.0f : 0.0f;  // off-diagonal
            }
        }
    }
}

extern "C" void kernel_launch(void* const* d_in, const int* in_sizes, int n_in,
                              void* d_out, int out_size) {
    const float* traj      = (const float*)d_in[0];
    const float* centroids = (const float*)d_in[1];
    const float* pen       = (const float*)d_in[2];
    // d_in[3] = off_diag_mask (~eye) — recomputed as (i != j) on device.

    float* out = (float*)d_out;
    const size_t P = (size_t)TT * NA * NA;
    int write_mask = ((size_t)out_size >= 2 * P) ? 1 : 0;

    veh_coll_kernel<<<NBLOCKS, NTHREADS>>>(traj, centroids, pen, out, write_mask);
}

// round 14
// speedup vs baseline: 1.1608x; 1.1608x over previous
#include <cuda_runtime.h>
#include <cstddef>
#include <math.h>

#define NA 192
#define TT 80
#define NC 5
#define TILE 32
#define HTILE 16
#define NTHREADS 256
#define NPAIRS 21

__constant__ unsigned char cIT[NPAIRS] = {0,0,0,0,0,0,1,1,1,1,1,2,2,2,2,3,3,3,4,4,5};
__constant__ unsigned char cJT[NPAIRS] = {0,1,2,3,4,5,1,2,3,4,5,2,3,4,5,3,4,5,4,5,5};

__global__ __launch_bounds__(NTHREADS) void veh_coll_kernel(
    const float* __restrict__ traj,        // (NA, T, 4)
    const float* __restrict__ centroids,   // (NA, NC, 4)
    const float* __restrict__ pen,         // (NA, NA)
    float* __restrict__ out,               // [pen (T,NA,NA)][mask (T,NA,NA)]
    int write_mask)
{
    __shared__ float4 sPose[2 * TILE];         // [0,32) = I tile, [32,64) = J tile
    __shared__ float  sG0[2 * TILE];           // s_0
    __shared__ float  sGd[2 * TILE];           // delta
    __shared__ float  sGi[2 * TILE];           // 1/delta
    __shared__ float  sTile[HTILE][TILE + 2];  // pv staged for transpose (stride 34)

    const int t    = blockIdx.x;
    const int pr2  = blockIdx.y;
    const int pr   = pr2 >> 1;
    const int ih   = (pr2 & 1) * HTILE;        // i half-offset within tile
    const int it   = cIT[pr];
    const int jt   = cJT[pr];
    const int tid  = threadIdx.x;

    // ---- Stage per-agent pose + uniform circle-grid parameters ----
    if (tid < 2 * TILE) {
        int side = tid >> 5, loc = tid & 31;
        int a = (side ? jt : it) * TILE + loc;
        float4 tr = *reinterpret_cast<const float4*>(traj + (a * TT + t) * 4);
        float inv = rsqrtf(tr.z * tr.z + tr.w * tr.w);
        sPose[tid] = make_float4(tr.x, tr.y, tr.z * inv, tr.w * inv);
        float s0 = centroids[(a * NC + 0) * 4];
        float s4 = centroids[(a * NC + 4) * 4];
        float dd = (s4 - s0) * 0.25f;          // uniform spacing (linspace frac)
        sG0[tid] = s0;
        sGd[tid] = dd;
        sGi[tid] = __frcp_rn(dd);
    }
    __syncthreads();

    // ---- lane = j local; each warp walks 2 i's of this half-tile ----
    const int jl   = tid & 31;
    const int warp = tid >> 5;
    const int jg   = jt * TILE + jl;

    const float4 pj   = sPose[TILE + jl];
    const float  sj0  = sG0[TILE + jl];
    const float  dj   = sGd[TILE + jl];
    const float  idj  = sGi[TILE + jl];
    const float  offj = -sj0 * idj;

    const unsigned P = (unsigned)TT * NA * NA;

    #pragma unroll
    for (int w = 0; w < HTILE / (NTHREADS / 32); ++w) {
        const int il = ih + warp + w * (NTHREADS / 32);
        const int ig = it * TILE + il;

        const float4 pi = sPose[il];           // broadcast
        const float si0 = sG0[il];
        const float di  = sGd[il];

        float dx = pi.x - pj.x;
        float dy = pi.y - pj.y;
        float a  = fmaf(dy, pi.w, dx * pi.z);     // base . h_i
        float b  = fmaf(dy, pj.w, dx * pj.z);     // base . h_j
        float g  = fmaf(pi.w, pj.w, pi.z * pj.z); // h_i . h_j
        float B  = fmaf(dy, dy, dx * dx);
        float a2  = a + a;
        float nb2 = -(b + b);
        float ng2 = -(g + g);
        float gi  = g * idj;                      // yn = x*gi + byn
        float byn = fmaf(b, idj, offj);

        float d2c[NC];
        #pragma unroll
        for (int c = 0; c < NC; c++) {
            float x  = fmaf((float)c, di, si0);   // i circle offset
            float yn = fmaf(x, gi, byn);          // grid coord of w* = b + g x
            float r  = fminf(fmaxf(yn, 0.0f), 4.0f);
            r        = rintf(r);                  // single FRND
            float wv = fmaf(r, dj, sj0);          // nearest j circle offset
            float uu = fmaf(x, x + a2, B);        // B + x^2 + 2ax
            float tm = fmaf(ng2, x, nb2);         // -2b - 2gx
            d2c[c]   = fmaf(wv, wv + tm, uu);     // exact min over d for this c
        }
        float m = fminf(fminf(fminf(d2c[0], d2c[1]), fminf(d2c[2], d2c[3])), d2c[4]);

        m = fmaxf(m, 1e-30f);
        float md = m * rsqrtf(m);                 // sqrt via 1 MUFU + 1 FMUL
        float pd = pen[ig * NA + jg];
        float pv = 1.0f - __fdividef(md, pd);
        const unsigned idx = ((unsigned)t * NA + ig) * NA + jg;
        out[idx] = pv;
        if (write_mask)
            out[P + idx] = (pv >= 0.0f && ig != jg) ? 1.0f : 0.0f;
        sTile[il - ih][jl] = pv;
    }

    // ---- Transposed write for off-diagonal tile pairs ----
    if (it != jt) {
        __syncthreads();
        #pragma unroll
        for (int q = 0; q < (HTILE * TILE) / NTHREADS; ++q) {
            int e  = tid + q * NTHREADS;
            int jj = e >> 4;                      // 0..31 (j index)
            int ii = e & 15;                      // 0..15 (i within half)
            float pv = sTile[ii][jj];             // stride 34: conflict-free
            const unsigned idxT =
                ((unsigned)t * NA + jt * TILE + jj) * NA + it * TILE + ih + ii;
            out[idxT] = pv;
            if (write_mask)
                out[P + idxT] = (pv >= 0.0f) ? 1.0f : 0.0f;  // it!=jt: off-diagonal
        }
    }
}

extern "C" void kernel_launch(void* const* d_in, const int* in_sizes, int n_in,
                              void* d_out, int out_size) {
    const float* traj      = (const float*)d_in[0];
    const float* centroids = (const float*)d_in[1];
    const float* pen       = (const float*)d_in[2];
    // d_in[3] = off_diag_mask (~eye) — recomputed as (i != j) on device.

    float* out = (float*)d_out;
    const size_t P = (size_t)TT * NA * NA;
    int write_mask = ((size_t)out_size >= 2 * P) ? 1 : 0;

    dim3 grid(TT, NPAIRS * 2);   // (80, 42) = 3360 half-tile blocks
    veh_coll_kernel<<<grid, NTHREADS>>>(traj, centroids, pen, out, write_mask);
}